// round 4
// baseline (speedup 1.0000x reference)
#include <cuda_runtime.h>
#include <math.h>

// Problem constants
#define BB   16
#define TT   512
#define HH   384
#define FF   384
#define KK3  3
#define DMAX 8
#define LL   (TT * DMAX)          // 4096
#define BT   (BB * TT)            // 8192
#define KKT  (HH * KK3)           // 1152 unified reduction dim
#define H4   (HH / 4)             // 96 float4 per row
#define OUT_OFF ((size_t)BB * LL * HH)   // length[] offset in d_out

// GEMM tiling
#define BM 128
#define BN 64
#define BK 32
#define ASTR 36                   // A smem row stride (pad: banks 4r+q distinct)
#define BSTR 72                   // B smem row stride (pad: banks 8q+r distinct)

// Scratch (static device globals; no allocation allowed)
__device__ unsigned g_wt1[KKT * FF];    // conv1 weights as [kk][f], tf32 bits
__device__ unsigned g_wt2[KKT * FF];    // conv2 weights as [kk][f], tf32 bits
__device__ float g_h1[BT * FF];         // conv1 output
__device__ float g_h2[BT * FF];         // conv2 output
__device__ int   g_tok[BB * LL];        // token index per expanded position (-1 = pad)

// ---------------------------------------------------------------------------
// tf32 round-to-nearest helper (result is fp32 bits with low mantissa zeroed)
// ---------------------------------------------------------------------------
__device__ __forceinline__ unsigned f2tf(float x) {
    unsigned r;
    asm("cvt.rna.tf32.f32 %0, %1;" : "=r"(r) : "f"(x));
    return r;
}

// ---------------------------------------------------------------------------
// Weight transpose + tf32 convert: w[f,c,tap] (OIW) -> wt[(tap*384+c)*384 + f]
// ---------------------------------------------------------------------------
__global__ void wtrans_kernel(const float* __restrict__ w, unsigned* __restrict__ wt) {
    int idx = blockIdx.x * 256 + threadIdx.x;
    if (idx >= FF * HH * KK3) return;
    int tap = idx % 3;
    int c   = (idx / 3) % HH;
    int f   = idx / (3 * HH);
    wt[(tap * HH + c) * FF + f] = f2tf(w[idx]);
}

__device__ __forceinline__ void mma_tf32(float c[4], const unsigned a[4], const unsigned b[2]) {
    asm volatile(
        "mma.sync.aligned.m16n8k8.row.col.f32.tf32.tf32.f32 "
        "{%0,%1,%2,%3}, {%4,%5,%6,%7}, {%8,%9}, {%0,%1,%2,%3};\n"
        : "+f"(c[0]), "+f"(c[1]), "+f"(c[2]), "+f"(c[3])
        : "r"(a[0]), "r"(a[1]), "r"(a[2]), "r"(a[3]), "r"(b[0]), "r"(b[1]));
}

// ---------------------------------------------------------------------------
// Conv-as-GEMM with tf32 tensor cores + register-prefetch pipeline.
// C[m,f] = sum_{tap,c} A[b, t+tap-1, c] * wt[tap*384+c, f] + bias[f]
// Grid (6, 64), 256 threads (8 warps: 4M x 2N), warp tile 32x32 via m16n8k8.
// ---------------------------------------------------------------------------
__global__ void __launch_bounds__(256) conv_gemm_tf32_kernel(
    const float* __restrict__ A, const unsigned* __restrict__ Bw,
    const float* __restrict__ bias, float* __restrict__ C) {
    __shared__ unsigned As[BM][ASTR];   // [m][k] tf32 bits
    __shared__ unsigned Bs[BK][BSTR];   // [k][n] tf32 bits

    const int tid  = threadIdx.x;
    const int lane = tid & 31;
    const int warp = tid >> 5;
    const int m0w  = (warp & 3) * 32;
    const int n0w  = (warp >> 2) * 32;
    const int m0   = blockIdx.y * BM;
    const int f0   = blockIdx.x * BN;
    const int b    = m0 >> 9;          // batch
    const int t0   = m0 & (TT - 1);    // t within batch

    const int r = lane >> 2;           // 0..7
    const int q = lane & 3;            // 0..3

    // per-thread load coordinates (fixed across iterations)
    const int am[4] = { (tid) >> 3, (tid + 256) >> 3, (tid + 512) >> 3, (tid + 768) >> 3 };
    const int ak    = (tid & 7) << 2;
    const int bk[2] = { tid >> 4, (tid + 256) >> 4 };
    const int bn    = (tid & 15) << 2;

    float acc[2][4][4];
#pragma unroll
    for (int mt = 0; mt < 2; mt++)
#pragma unroll
        for (int nt = 0; nt < 4; nt++)
#pragma unroll
            for (int i = 0; i < 4; i++) acc[mt][nt][i] = 0.0f;

    float4 av[4];
    uint4  bv[2];

    // prefetch tile 0
    {
        const int tap = 0, c0 = 0;
#pragma unroll
        for (int i = 0; i < 4; i++) {
            const int trow = t0 + am[i] + tap - 1;
            av[i] = make_float4(0.f, 0.f, 0.f, 0.f);
            if (trow >= 0 && trow < TT)
                av[i] = *reinterpret_cast<const float4*>(
                    A + (size_t)((b << 9) + trow) * HH + c0 + ak);
        }
#pragma unroll
        for (int i = 0; i < 2; i++)
            bv[i] = *reinterpret_cast<const uint4*>(
                Bw + (size_t)(tap * HH + c0 + bk[i]) * FF + f0 + bn);
    }

    for (int kt = 0; kt < KKT / BK; kt++) {          // 36 iterations
        // ---- store prefetched tile to smem ----
#pragma unroll
        for (int i = 0; i < 4; i++) {
            uint4 u;
            u.x = f2tf(av[i].x); u.y = f2tf(av[i].y);
            u.z = f2tf(av[i].z); u.w = f2tf(av[i].w);
            *reinterpret_cast<uint4*>(&As[am[i]][ak]) = u;
        }
#pragma unroll
        for (int i = 0; i < 2; i++)
            *reinterpret_cast<uint4*>(&Bs[bk[i]][bn]) = bv[i];
        __syncthreads();

        // ---- prefetch next tile into registers (overlaps with compute) ----
        if (kt + 1 < KKT / BK) {
            const int kk0 = (kt + 1) * BK;
            const int tap = kk0 / HH;
            const int c0  = kk0 - tap * HH;
#pragma unroll
            for (int i = 0; i < 4; i++) {
                const int trow = t0 + am[i] + tap - 1;
                av[i] = make_float4(0.f, 0.f, 0.f, 0.f);
                if (trow >= 0 && trow < TT)
                    av[i] = *reinterpret_cast<const float4*>(
                        A + (size_t)((b << 9) + trow) * HH + c0 + ak);
            }
#pragma unroll
            for (int i = 0; i < 2; i++)
                bv[i] = *reinterpret_cast<const uint4*>(
                    Bw + (size_t)(tap * HH + c0 + bk[i]) * FF + f0 + bn);
        }

        // ---- compute: 4 k-steps of 8 ----
#pragma unroll
        for (int s = 0; s < 4; s++) {
            const int ks = s * 8;
            unsigned a[2][4], bf[4][2];
#pragma unroll
            for (int mt = 0; mt < 2; mt++) {
                const int mr = m0w + mt * 16 + r;
                a[mt][0] = As[mr][ks + q];
                a[mt][1] = As[mr + 8][ks + q];
                a[mt][2] = As[mr][ks + q + 4];
                a[mt][3] = As[mr + 8][ks + q + 4];
            }
#pragma unroll
            for (int nt = 0; nt < 4; nt++) {
                const int nc = n0w + nt * 8 + r;
                bf[nt][0] = Bs[ks + q][nc];
                bf[nt][1] = Bs[ks + q + 4][nc];
            }
#pragma unroll
            for (int mt = 0; mt < 2; mt++)
#pragma unroll
                for (int nt = 0; nt < 4; nt++)
                    mma_tf32(acc[mt][nt], a[mt], bf[nt]);
        }
        __syncthreads();
    }

    // ---- epilogue: add bias, write C ----
#pragma unroll
    for (int mt = 0; mt < 2; mt++) {
        const int gm0 = m0 + m0w + mt * 16 + r;
#pragma unroll
        for (int nt = 0; nt < 4; nt++) {
            const int gf = f0 + n0w + nt * 8 + 2 * q;
            const float2 bvv = *reinterpret_cast<const float2*>(bias + gf);
            float2 o0, o1;
            o0.x = acc[mt][nt][0] + bvv.x;
            o0.y = acc[mt][nt][1] + bvv.y;
            o1.x = acc[mt][nt][2] + bvv.x;
            o1.y = acc[mt][nt][3] + bvv.y;
            *reinterpret_cast<float2*>(C + (size_t)gm0 * FF + gf) = o0;
            *reinterpret_cast<float2*>(C + (size_t)(gm0 + 8) * FF + gf) = o1;
        }
    }
}

// ---------------------------------------------------------------------------
// Block reduction helper: 128 threads (4 warps)
// ---------------------------------------------------------------------------
__device__ __forceinline__ float block_sum128(float v, float* red, int tid) {
#pragma unroll
    for (int o = 16; o > 0; o >>= 1) v += __shfl_xor_sync(0xffffffffu, v, o);
    if ((tid & 31) == 0) red[tid >> 5] = v;
    __syncthreads();
    v = red[0] + red[1] + red[2] + red[3];
    __syncthreads();
    return v;
}

__device__ __forceinline__ float gelu_exact(float y) {
    return 0.5f * y * (1.0f + erff(y * 0.70710678118654752f));
}

// LayerNorm + exact GELU in place. One block per row, 128 threads (3 elems each).
__global__ void __launch_bounds__(128) ln_gelu_kernel(
    float* __restrict__ h, const float* __restrict__ g, const float* __restrict__ bb) {
    __shared__ float red[4];
    const int row = blockIdx.x, tid = threadIdx.x;
    float* p = h + (size_t)row * FF;
    float v0 = p[tid], v1 = p[tid + 128], v2 = p[tid + 256];
    const float mu = block_sum128(v0 + v1 + v2, red, tid) * (1.0f / FF);
    const float d0 = v0 - mu, d1 = v1 - mu, d2 = v2 - mu;
    const float var = block_sum128(d0 * d0 + d1 * d1 + d2 * d2, red, tid) * (1.0f / FF);
    const float rs = rsqrtf(var + 1e-5f);
    const float y0 = d0 * rs * g[tid] + bb[tid];
    const float y1 = d1 * rs * g[tid + 128] + bb[tid + 128];
    const float y2 = d2 * rs * g[tid + 256] + bb[tid + 256];
    p[tid]       = gelu_exact(y0);
    p[tid + 128] = gelu_exact(y1);
    p[tid + 256] = gelu_exact(y2);
}

// LayerNorm + GELU + linear(384->1) + ReLU -> length[row]
__global__ void __launch_bounds__(128) ln_gelu_lin_kernel(
    const float* __restrict__ h, const float* __restrict__ g, const float* __restrict__ bb,
    const float* __restrict__ lw, const float* __restrict__ lb, float* __restrict__ lenout) {
    __shared__ float red[4];
    const int row = blockIdx.x, tid = threadIdx.x;
    const float* p = h + (size_t)row * FF;
    float v0 = p[tid], v1 = p[tid + 128], v2 = p[tid + 256];
    const float mu = block_sum128(v0 + v1 + v2, red, tid) * (1.0f / FF);
    const float d0 = v0 - mu, d1 = v1 - mu, d2 = v2 - mu;
    const float var = block_sum128(d0 * d0 + d1 * d1 + d2 * d2, red, tid) * (1.0f / FF);
    const float rs = rsqrtf(var + 1e-5f);
    const float q0 = gelu_exact(d0 * rs * g[tid] + bb[tid]);
    const float q1 = gelu_exact(d1 * rs * g[tid + 128] + bb[tid + 128]);
    const float q2 = gelu_exact(d2 * rs * g[tid + 256] + bb[tid + 256]);
    const float dot = block_sum128(q0 * lw[tid] + q1 * lw[tid + 128] + q2 * lw[tid + 256],
                                   red, tid);
    if (tid == 0) lenout[row] = fmaxf(dot + lb[0], 0.0f);
}

// ---------------------------------------------------------------------------
// Duration scan + token map. One block per batch, 512 threads.
// ---------------------------------------------------------------------------
__global__ void __launch_bounds__(512) build_tok_kernel(
    const float* __restrict__ td, int* __restrict__ tok) {
    __shared__ int sc[TT];
    const int b = blockIdx.x, t = threadIdx.x;
    const int d = (int)rintf(expf(td[b * TT + t]));
    sc[t] = d;
    __syncthreads();
    for (int off = 1; off < TT; off <<= 1) {
        int v = sc[t];
        int add = (t >= off) ? sc[t - off] : 0;
        __syncthreads();
        sc[t] = v + add;
        __syncthreads();
    }
    const int end = sc[t];
    const int start = end - d;
    for (int l = start; l < end; l++) tok[b * LL + l] = t;
    __syncthreads();
    const int total = sc[TT - 1];
    for (int l = total + t; l < LL; l += TT) tok[b * LL + l] = -1;
}

// ---------------------------------------------------------------------------
// Expansion: out[b,l,:] = x[b,tok[b][l],:] (or zeros). float4 per thread.
// ---------------------------------------------------------------------------
__global__ void __launch_bounds__(256) expand_kernel(
    const float* __restrict__ x, const int* __restrict__ tok, float* __restrict__ out) {
    const unsigned idx = blockIdx.x * 256u + threadIdx.x;
    const int h4 = idx % H4;
    const int l  = (idx / H4) & (LL - 1);
    const int b  = idx / (H4 * LL);
    const int t  = tok[b * LL + l];
    float4 v = make_float4(0.f, 0.f, 0.f, 0.f);
    if (t >= 0)
        v = reinterpret_cast<const float4*>(x)[(size_t)(b * TT + t) * H4 + h4];
    reinterpret_cast<float4*>(out)[idx] = v;
}

// ---------------------------------------------------------------------------
extern "C" void kernel_launch(void* const* d_in, const int* in_sizes, int n_in,
                              void* d_out, int out_size) {
    const float* x   = (const float*)d_in[0];
    const float* td  = (const float*)d_in[1];
    const float* w1  = (const float*)d_in[2];
    const float* b1  = (const float*)d_in[3];
    const float* g1  = (const float*)d_in[4];
    const float* bb1 = (const float*)d_in[5];
    const float* w2  = (const float*)d_in[6];
    const float* b2  = (const float*)d_in[7];
    const float* g2  = (const float*)d_in[8];
    const float* bb2 = (const float*)d_in[9];
    const float* lw  = (const float*)d_in[10];
    const float* lb  = (const float*)d_in[11];

    float* out = (float*)d_out;
    float* lenout = out + OUT_OFF;

    unsigned *wt1p, *wt2p;
    float *h1p, *h2p;
    int* tokp;
    cudaGetSymbolAddress((void**)&wt1p, g_wt1);
    cudaGetSymbolAddress((void**)&wt2p, g_wt2);
    cudaGetSymbolAddress((void**)&h1p,  g_h1);
    cudaGetSymbolAddress((void**)&h2p,  g_h2);
    cudaGetSymbolAddress((void**)&tokp, g_tok);

    const int wele = FF * HH * KK3;
    wtrans_kernel<<<(wele + 255) / 256, 256>>>(w1, wt1p);
    wtrans_kernel<<<(wele + 255) / 256, 256>>>(w2, wt2p);

    dim3 ggrid(FF / BN, BT / BM);   // (6, 64)
    conv_gemm_tf32_kernel<<<ggrid, 256>>>(x, wt1p, b1, h1p);
    ln_gelu_kernel<<<BT, 128>>>(h1p, g1, bb1);
    conv_gemm_tf32_kernel<<<ggrid, 256>>>(h1p, wt2p, b2, h2p);
    ln_gelu_lin_kernel<<<BT, 128>>>(h2p, g2, bb2, lw, lb, lenout);

    build_tok_kernel<<<BB, TT>>>(td, tokp);
    expand_kernel<<<(BB * LL * H4) / 256, 256>>>(x, tokp, out);
}

// round 5
// speedup vs baseline: 1.2427x; 1.2427x over previous
#include <cuda_runtime.h>
#include <math.h>

// Problem constants
#define BB   16
#define TT   512
#define HH   384
#define FF   384
#define KK3  3
#define DMAX 8
#define LL   (TT * DMAX)          // 4096
#define BT   (BB * TT)            // 8192
#define KKT  (HH * KK3)           // 1152 unified reduction dim
#define H4   (HH / 4)             // 96 float4 per row
#define OUT_OFF ((size_t)BB * LL * HH)   // length[] offset in d_out

// GEMM tiling
#define BM 128
#define BN 64
#define BK 32
#define NKT (KKT / BK)            // 36 k-iterations

// Scratch (static device globals; no allocation allowed)
__device__ unsigned g_wt1[FF * KKT];    // conv1 weights, f-major, k-pair-permuted, tf32 bits
__device__ unsigned g_wt2[FF * KKT];    // conv2 weights, same layout
__device__ unsigned g_xr[BT * HH];      // x, tf32-rounded + k-pair-permuted
__device__ float g_h1[BT * FF];         // conv1 out (plain fp32) -> ln_gelu -> tf32 bits permuted
__device__ float g_h2[BT * FF];         // conv2 output (plain fp32)
__device__ int   g_tok[BB * LL];        // token index per expanded position (-1 = pad)

// ---------------------------------------------------------------------------
// tf32 round helper + k-pair permutation (within each 8-block: [0,4,1,5,2,6,3,7])
// ---------------------------------------------------------------------------
__device__ __forceinline__ unsigned f2tf(float x) {
    unsigned r;
    asm("cvt.rna.tf32.f32 %0, %1;" : "=r"(r) : "f"(x));
    return r;
}

__device__ __forceinline__ int perm8(int c) {
    int u = c & 7;
    return (c & ~7) | ((u < 4) ? (u << 1) : (((u - 4) << 1) | 1));
}

// cp.async 16B with zero-fill when sz==0
__device__ __forceinline__ void cp16(void* dst, const void* src, int sz) {
    unsigned d = (unsigned)__cvta_generic_to_shared(dst);
    asm volatile("cp.async.cg.shared.global [%0], [%1], 16, %2;\n"
                 :: "r"(d), "l"(src), "r"(sz));
}

// ---------------------------------------------------------------------------
// x pre-round: xr[m, perm8(c)] = tf32(x[m, c])
// ---------------------------------------------------------------------------
__global__ void round_x_kernel(const float* __restrict__ x, unsigned* __restrict__ xr) {
    int i = blockIdx.x * 256 + threadIdx.x;     // grid covers BT*HH exactly
    int m = i / HH, c = i % HH;
    xr[m * HH + perm8(c)] = f2tf(x[i]);
}

// ---------------------------------------------------------------------------
// Weight transpose (both convs in one launch):
// w[f,c,tap] (OIW) -> wt[f * 1152 + tap*384 + perm8(c)] as tf32 bits
// ---------------------------------------------------------------------------
__global__ void wtrans_kernel(const float* __restrict__ w1, const float* __restrict__ w2,
                              unsigned* __restrict__ o1, unsigned* __restrict__ o2) {
    const int N = FF * HH * KK3;
    int i = blockIdx.x * 256 + threadIdx.x;
    const float* w = w1; unsigned* o = o1;
    int idx = i;
    if (i >= N) { idx = i - N; w = w2; o = o2; }
    int f   = idx / (HH * 3);
    int rem = idx % (HH * 3);
    int c   = rem / 3;
    int tap = rem % 3;
    o[f * KKT + tap * HH + perm8(c)] = f2tf(w[idx]);
}

__device__ __forceinline__ void mma_tf32(float c[4], const unsigned a[4], const unsigned b[2]) {
    asm volatile(
        "mma.sync.aligned.m16n8k8.row.col.f32.tf32.tf32.f32 "
        "{%0,%1,%2,%3}, {%4,%5,%6,%7}, {%8,%9}, {%0,%1,%2,%3};\n"
        : "+f"(c[0]), "+f"(c[1]), "+f"(c[2]), "+f"(c[3])
        : "r"(a[0]), "r"(a[1]), "r"(a[2]), "r"(a[3]), "r"(b[0]), "r"(b[1]));
}

// ---------------------------------------------------------------------------
// Conv-as-GEMM, tf32 mma, cp.async double-buffered, LDS.64 fragment loads.
// A (activations): [row][HH] tf32 bits, k-pair-permuted per 8-block.
// B (weights): [f][KKT] tf32 bits, k-pair-permuted.
// C[m,f] = sum A[b, t+tap-1, :] . B[f, tap*384+:] + bias[f]
// Grid (6, 64), 256 threads (8 warps: 4M x 2N), warp tile 32x32.
// ---------------------------------------------------------------------------
__global__ void __launch_bounds__(256) conv_gemm_kernel(
    const unsigned* __restrict__ Axr, const unsigned* __restrict__ Bw,
    const float* __restrict__ bias, float* __restrict__ C) {
    // uint2 element j (unswizzled) = 4s+q holds (k=8s+q, k=8s+q+4); swizzle j^((row&3)<<2)
    __shared__ __align__(16) uint2 SA[2][BM][16];   // 32 KB
    __shared__ __align__(16) uint2 SB[2][BN][16];   // 16 KB

    const int tid  = threadIdx.x;
    const int lane = tid & 31;
    const int warp = tid >> 5;
    const int m0w  = (warp & 3) * 32;
    const int n0w  = (warp >> 2) * 32;
    const int m0   = blockIdx.y * BM;
    const int f0   = blockIdx.x * BN;
    const int b    = m0 >> 9;
    const int t0   = m0 & (TT - 1);

    const int r = lane >> 2;
    const int q = lane & 3;

    float acc[2][4][4];
#pragma unroll
    for (int mt = 0; mt < 2; mt++)
#pragma unroll
        for (int nt = 0; nt < 4; nt++)
#pragma unroll
            for (int i = 0; i < 4; i++) acc[mt][nt][i] = 0.0f;

    // fixed per-thread load coords
    const int amr[4] = { tid >> 3, (tid + 256) >> 3, (tid + 512) >> 3, (tid + 768) >> 3 };
    const int at     = tid & 7;                 // 16B chunk within row
    const int bnr[2] = { tid >> 3, (tid + 256) >> 3 };

#define LOAD_TILE(KT, BUF) do {                                               \
        const int kk0 = (KT) * BK;                                            \
        const int tap = kk0 / HH;                                             \
        const int c0  = kk0 - tap * HH;                                       \
        _Pragma("unroll")                                                     \
        for (int i = 0; i < 4; i++) {                                         \
            const int m    = amr[i];                                          \
            const int trow = t0 + m + tap - 1;                                \
            const int ok   = (trow >= 0 && trow < TT);                        \
            const unsigned* src = Axr +                                       \
                (size_t)((b << 9) + (ok ? trow : 0)) * HH + c0 + 4 * at;      \
            cp16(&SA[BUF][m][(2 * at) ^ ((m & 3) << 2)], src, ok ? 16 : 0);   \
        }                                                                     \
        _Pragma("unroll")                                                     \
        for (int i = 0; i < 2; i++) {                                         \
            const int n = bnr[i];                                             \
            const unsigned* src = Bw + (size_t)(f0 + n) * KKT + kk0 + 4 * at; \
            cp16(&SB[BUF][n][(2 * at) ^ ((n & 3) << 2)], src, 16);            \
        }                                                                     \
        asm volatile("cp.async.commit_group;\n");                             \
    } while (0)

    LOAD_TILE(0, 0);

    for (int kt = 0; kt < NKT; kt++) {
        const int cur = kt & 1;
        if (kt + 1 < NKT) {
            LOAD_TILE(kt + 1, cur ^ 1);
            asm volatile("cp.async.wait_group 1;\n");
        } else {
            asm volatile("cp.async.wait_group 0;\n");
        }
        __syncthreads();

#pragma unroll
        for (int s = 0; s < 4; s++) {
            unsigned a[2][4], bf[4][2];
#pragma unroll
            for (int mt = 0; mt < 2; mt++) {
                const int mr  = m0w + mt * 16 + r;
                const int idx = ((s ^ (mr & 3)) << 2) | q;
                const uint2 va0 = SA[cur][mr][idx];
                const uint2 va1 = SA[cur][mr + 8][idx];
                a[mt][0] = va0.x; a[mt][1] = va1.x; a[mt][2] = va0.y; a[mt][3] = va1.y;
            }
#pragma unroll
            for (int nt = 0; nt < 4; nt++) {
                const int nc  = n0w + nt * 8 + r;
                const uint2 vb = SB[cur][nc][((s ^ (nc & 3)) << 2) | q];
                bf[nt][0] = vb.x; bf[nt][1] = vb.y;
            }
#pragma unroll
            for (int mt = 0; mt < 2; mt++)
#pragma unroll
                for (int nt = 0; nt < 4; nt++)
                    mma_tf32(acc[mt][nt], a[mt], bf[nt]);
        }
        __syncthreads();
    }

    // epilogue: add bias, write plain fp32
#pragma unroll
    for (int mt = 0; mt < 2; mt++) {
        const int gm0 = m0 + m0w + mt * 16 + r;
#pragma unroll
        for (int nt = 0; nt < 4; nt++) {
            const int gf = f0 + n0w + nt * 8 + 2 * q;
            const float2 bvv = *reinterpret_cast<const float2*>(bias + gf);
            float2 o0, o1;
            o0.x = acc[mt][nt][0] + bvv.x;
            o0.y = acc[mt][nt][1] + bvv.y;
            o1.x = acc[mt][nt][2] + bvv.x;
            o1.y = acc[mt][nt][3] + bvv.y;
            *reinterpret_cast<float2*>(C + (size_t)gm0 * FF + gf) = o0;
            *reinterpret_cast<float2*>(C + (size_t)(gm0 + 8) * FF + gf) = o1;
        }
    }
#undef LOAD_TILE
}

// ---------------------------------------------------------------------------
// Block reduction helper: 128 threads (4 warps)
// ---------------------------------------------------------------------------
__device__ __forceinline__ float block_sum128(float v, float* red, int tid) {
#pragma unroll
    for (int o = 16; o > 0; o >>= 1) v += __shfl_xor_sync(0xffffffffu, v, o);
    if ((tid & 31) == 0) red[tid >> 5] = v;
    __syncthreads();
    v = red[0] + red[1] + red[2] + red[3];
    __syncthreads();
    return v;
}

__device__ __forceinline__ float gelu_exact(float y) {
    return 0.5f * y * (1.0f + erff(y * 0.70710678118654752f));
}

// LayerNorm + exact GELU in place; writes tf32-rounded bits at k-pair-permuted
// columns (so conv2 can cp.async the rows directly). One block per row.
__global__ void __launch_bounds__(128) ln_gelu_kernel(
    float* __restrict__ h, const float* __restrict__ g, const float* __restrict__ bb) {
    __shared__ float red[4];
    const int row = blockIdx.x, tid = threadIdx.x;
    float* p = h + (size_t)row * FF;
    float v0 = p[tid], v1 = p[tid + 128], v2 = p[tid + 256];
    const float mu = block_sum128(v0 + v1 + v2, red, tid) * (1.0f / FF);
    const float d0 = v0 - mu, d1 = v1 - mu, d2 = v2 - mu;
    const float var = block_sum128(d0 * d0 + d1 * d1 + d2 * d2, red, tid) * (1.0f / FF);
    const float rs = rsqrtf(var + 1e-5f);
    const float y0 = d0 * rs * g[tid] + bb[tid];
    const float y1 = d1 * rs * g[tid + 128] + bb[tid + 128];
    const float y2 = d2 * rs * g[tid + 256] + bb[tid + 256];
    // all reads of p happened before the reductions' barriers -> in-place permute safe
    p[perm8(tid)]       = __uint_as_float(f2tf(gelu_exact(y0)));
    p[perm8(tid + 128)] = __uint_as_float(f2tf(gelu_exact(y1)));
    p[perm8(tid + 256)] = __uint_as_float(f2tf(gelu_exact(y2)));
}

// LayerNorm + GELU + linear(384->1) + ReLU -> length[row]
__global__ void __launch_bounds__(128) ln_gelu_lin_kernel(
    const float* __restrict__ h, const float* __restrict__ g, const float* __restrict__ bb,
    const float* __restrict__ lw, const float* __restrict__ lb, float* __restrict__ lenout) {
    __shared__ float red[4];
    const int row = blockIdx.x, tid = threadIdx.x;
    const float* p = h + (size_t)row * FF;
    float v0 = p[tid], v1 = p[tid + 128], v2 = p[tid + 256];
    const float mu = block_sum128(v0 + v1 + v2, red, tid) * (1.0f / FF);
    const float d0 = v0 - mu, d1 = v1 - mu, d2 = v2 - mu;
    const float var = block_sum128(d0 * d0 + d1 * d1 + d2 * d2, red, tid) * (1.0f / FF);
    const float rs = rsqrtf(var + 1e-5f);
    const float q0 = gelu_exact(d0 * rs * g[tid] + bb[tid]);
    const float q1 = gelu_exact(d1 * rs * g[tid + 128] + bb[tid + 128]);
    const float q2 = gelu_exact(d2 * rs * g[tid + 256] + bb[tid + 256]);
    const float dot = block_sum128(q0 * lw[tid] + q1 * lw[tid + 128] + q2 * lw[tid + 256],
                                   red, tid);
    if (tid == 0) lenout[row] = fmaxf(dot + lb[0], 0.0f);
}

// ---------------------------------------------------------------------------
// Duration scan + token map. One block per batch, 512 threads.
// ---------------------------------------------------------------------------
__global__ void __launch_bounds__(512) build_tok_kernel(
    const float* __restrict__ td, int* __restrict__ tok) {
    __shared__ int sc[TT];
    const int b = blockIdx.x, t = threadIdx.x;
    const int d = (int)rintf(expf(td[b * TT + t]));
    sc[t] = d;
    __syncthreads();
    for (int off = 1; off < TT; off <<= 1) {
        int v = sc[t];
        int add = (t >= off) ? sc[t - off] : 0;
        __syncthreads();
        sc[t] = v + add;
        __syncthreads();
    }
    const int end = sc[t];
    const int start = end - d;
    for (int l = start; l < end; l++) tok[b * LL + l] = t;
    __syncthreads();
    const int total = sc[TT - 1];
    for (int l = total + t; l < LL; l += TT) tok[b * LL + l] = -1;
}

// ---------------------------------------------------------------------------
// Expansion: out[b,l,:] = x[b,tok[b][l],:] (or zeros). float4 per thread.
// ---------------------------------------------------------------------------
__global__ void __launch_bounds__(256) expand_kernel(
    const float* __restrict__ x, const int* __restrict__ tok, float* __restrict__ out) {
    const unsigned idx = blockIdx.x * 256u + threadIdx.x;
    const int h4 = idx % H4;
    const int l  = (idx / H4) & (LL - 1);
    const int b  = idx / (H4 * LL);
    const int t  = tok[b * LL + l];
    float4 v = make_float4(0.f, 0.f, 0.f, 0.f);
    if (t >= 0)
        v = reinterpret_cast<const float4*>(x)[(size_t)(b * TT + t) * H4 + h4];
    reinterpret_cast<float4*>(out)[idx] = v;
}

// ---------------------------------------------------------------------------
extern "C" void kernel_launch(void* const* d_in, const int* in_sizes, int n_in,
                              void* d_out, int out_size) {
    const float* x   = (const float*)d_in[0];
    const float* td  = (const float*)d_in[1];
    const float* w1  = (const float*)d_in[2];
    const float* b1  = (const float*)d_in[3];
    const float* g1  = (const float*)d_in[4];
    const float* bb1 = (const float*)d_in[5];
    const float* w2  = (const float*)d_in[6];
    const float* b2  = (const float*)d_in[7];
    const float* g2  = (const float*)d_in[8];
    const float* bb2 = (const float*)d_in[9];
    const float* lw  = (const float*)d_in[10];
    const float* lb  = (const float*)d_in[11];

    float* out = (float*)d_out;
    float* lenout = out + OUT_OFF;

    unsigned *wt1p, *wt2p, *xrp;
    float *h1p, *h2p;
    int* tokp;
    cudaGetSymbolAddress((void**)&wt1p, g_wt1);
    cudaGetSymbolAddress((void**)&wt2p, g_wt2);
    cudaGetSymbolAddress((void**)&xrp,  g_xr);
    cudaGetSymbolAddress((void**)&h1p,  g_h1);
    cudaGetSymbolAddress((void**)&h2p,  g_h2);
    cudaGetSymbolAddress((void**)&tokp, g_tok);

    round_x_kernel<<<(BT * HH) / 256, 256>>>(x, xrp);
    wtrans_kernel<<<(2 * FF * HH * KK3) / 256, 256>>>(w1, w2, wt1p, wt2p);

    dim3 ggrid(FF / BN, BT / BM);   // (6, 64)
    conv_gemm_kernel<<<ggrid, 256>>>(xrp, wt1p, b1, h1p);
    ln_gelu_kernel<<<BT, 128>>>(h1p, g1, bb1);
    conv_gemm_kernel<<<ggrid, 256>>>((const unsigned*)h1p, wt2p, b2, h2p);
    ln_gelu_lin_kernel<<<BT, 128>>>(h2p, g2, bb2, lw, lb, lenout);

    build_tok_kernel<<<BB, TT>>>(td, tokp);
    expand_kernel<<<(BB * LL * H4) / 256, 256>>>(x, tokp, out);
}

// round 6
// speedup vs baseline: 1.8011x; 1.4494x over previous
#include <cuda_runtime.h>
#include <cuda_fp16.h>
#include <math.h>

// Problem constants
#define BB   16
#define TT   512
#define HH   384
#define FF   384
#define KK3  3
#define DMAX 8
#define LL   (TT * DMAX)          // 4096
#define BT   (BB * TT)            // 8192
#define KKT  (HH * KK3)           // 1152 unified reduction dim
#define H4   (HH / 4)             // 96 float4 per row
#define OUT_OFF ((size_t)BB * LL * HH)   // length[] offset in d_out

// GEMM tiling (fp16: K=16 per mma, BK=64 keeps 128B smem rows)
#define BM 128
#define BN 64
#define BK 64
#define NKT (KKT / BK)            // 18 k-iterations

// Scratch (static device globals; no allocation allowed)
__device__ __half g_wt1h[FF * KKT];     // conv1 weights, f-major, pair-permuted fp16
__device__ __half g_wt2h[FF * KKT];     // conv2 weights, same layout
__device__ __half g_xh[BT * HH];        // x, fp16 + pair-permuted
__device__ float  g_h1[BT * FF];        // conv1 out (fp32)
__device__ __half g_h1h[BT * FF];       // ln_gelu(conv1) fp16 pair-permuted
__device__ float  g_h2[BT * FF];        // conv2 output (fp32)
__device__ int    g_tok[BB * LL];       // token index per expanded position (-1 = pad)

// ---------------------------------------------------------------------------
// half-index permutation: within each 16-half block, k-pairs [0..7] are stored
// interleaved as [0,4,1,5,2,6,3,7] so one LDS.64 (uint2) yields pairs (q, q+4)
// = halves {2q,2q+1, 2q+8,2q+9} — exactly one m16n8k16 fragment piece.
// ---------------------------------------------------------------------------
__device__ __forceinline__ int perm8(int c) {
    int u = c & 7;
    return (c & ~7) | ((u < 4) ? (u << 1) : (((u - 4) << 1) | 1));
}
__device__ __forceinline__ int permH(int k) {
    return (perm8(k >> 1) << 1) | (k & 1);
}

// cp.async 16B with zero-fill when sz==0
__device__ __forceinline__ void cp16(void* dst, const void* src, int sz) {
    unsigned d = (unsigned)__cvta_generic_to_shared(dst);
    asm volatile("cp.async.cg.shared.global [%0], [%1], 16, %2;\n"
                 :: "r"(d), "l"(src), "r"(sz));
}

// ---------------------------------------------------------------------------
// x pre-convert: xh[m, permH(c)] = fp16(x[m, c])
// ---------------------------------------------------------------------------
__global__ void round_x_kernel(const float* __restrict__ x, __half* __restrict__ xh) {
    int i = blockIdx.x * 256 + threadIdx.x;     // grid covers BT*HH exactly
    int m = i / HH, c = i % HH;
    xh[m * HH + permH(c)] = __float2half_rn(x[i]);
}

// ---------------------------------------------------------------------------
// Weight transpose (both convs in one launch):
// w[f,c,tap] (OIW) -> wt[f * 1152 + permH(tap*384 + c)] as fp16
// (tap*384 is a multiple of 16, so permH acts within blocks: permH(tap*HH+c)
//  = tap*HH + permH(c))
// ---------------------------------------------------------------------------
__global__ void wtrans_kernel(const float* __restrict__ w1, const float* __restrict__ w2,
                              __half* __restrict__ o1, __half* __restrict__ o2) {
    const int N = FF * HH * KK3;
    int i = blockIdx.x * 256 + threadIdx.x;
    const float* w = w1; __half* o = o1;
    int idx = i;
    if (i >= N) { idx = i - N; w = w2; o = o2; }
    int f   = idx / (HH * 3);
    int rem = idx % (HH * 3);
    int c   = rem / 3;
    int tap = rem % 3;
    o[f * KKT + tap * HH + permH(c)] = __float2half_rn(w[idx]);
}

__device__ __forceinline__ void mma_f16(float c[4], const unsigned a[4], const unsigned b[2]) {
    asm volatile(
        "mma.sync.aligned.m16n8k16.row.col.f32.f16.f16.f32 "
        "{%0,%1,%2,%3}, {%4,%5,%6,%7}, {%8,%9}, {%0,%1,%2,%3};\n"
        : "+f"(c[0]), "+f"(c[1]), "+f"(c[2]), "+f"(c[3])
        : "r"(a[0]), "r"(a[1]), "r"(a[2]), "r"(a[3]), "r"(b[0]), "r"(b[1]));
}

// ---------------------------------------------------------------------------
// Conv-as-GEMM, fp16 m16n8k16, cp.async double-buffered, LDS.64 fragments.
// A (activations): [row][HH] fp16, pair-permuted. B (weights): [f][KKT] fp16.
// C[m,f] = sum A[b, t+tap-1, :] . B[f, tap*384+:] + bias[f]   (fp32 accum)
// Grid (6, 64), 256 threads (8 warps: 4M x 2N), warp tile 32x32.
// ---------------------------------------------------------------------------
__global__ void __launch_bounds__(256) conv_gemm_kernel(
    const __half* __restrict__ Axh, const __half* __restrict__ Bwh,
    const float* __restrict__ bias, float* __restrict__ C) {
    // uint2 j (unswizzled) = 4s+q holds k-pairs (8s+q, 8s+q+4) of the row's BK=64
    // halves (s = k16 step 0..3). swizzle: j ^ ((row&3)<<2). Row = 128B.
    __shared__ __align__(16) uint2 SA[2][BM][16];   // 32 KB
    __shared__ __align__(16) uint2 SB[2][BN][16];   // 16 KB

    const int tid  = threadIdx.x;
    const int lane = tid & 31;
    const int warp = tid >> 5;
    const int m0w  = (warp & 3) * 32;
    const int n0w  = (warp >> 2) * 32;
    const int m0   = blockIdx.y * BM;
    const int f0   = blockIdx.x * BN;
    const int b    = m0 >> 9;
    const int t0   = m0 & (TT - 1);

    const int r = lane >> 2;
    const int q = lane & 3;

    float acc[2][4][4];
#pragma unroll
    for (int mt = 0; mt < 2; mt++)
#pragma unroll
        for (int nt = 0; nt < 4; nt++)
#pragma unroll
            for (int i = 0; i < 4; i++) acc[mt][nt][i] = 0.0f;

    // fixed per-thread load coords (8 x 16B chunks per 128B row)
    const int amr[4] = { tid >> 3, (tid + 256) >> 3, (tid + 512) >> 3, (tid + 768) >> 3 };
    const int at     = tid & 7;
    const int bnr[2] = { tid >> 3, (tid + 256) >> 3 };

#define LOAD_TILE(KT, BUF) do {                                                \
        const int kk0 = (KT) * BK;                                             \
        const int tap = kk0 / HH;                                              \
        const int c0  = kk0 - tap * HH;                                        \
        _Pragma("unroll")                                                      \
        for (int i = 0; i < 4; i++) {                                          \
            const int m    = amr[i];                                           \
            const int trow = t0 + m + tap - 1;                                 \
            const int ok   = (trow >= 0 && trow < TT);                         \
            const __half* src = Axh +                                          \
                (size_t)((b << 9) + (ok ? trow : 0)) * HH + c0 + 8 * at;       \
            cp16(&SA[BUF][m][(2 * at) ^ ((m & 3) << 2)], src, ok ? 16 : 0);    \
        }                                                                      \
        _Pragma("unroll")                                                      \
        for (int i = 0; i < 2; i++) {                                          \
            const int n = bnr[i];                                              \
            const __half* src = Bwh + (size_t)(f0 + n) * KKT + kk0 + 8 * at;   \
            cp16(&SB[BUF][n][(2 * at) ^ ((n & 3) << 2)], src, 16);             \
        }                                                                      \
        asm volatile("cp.async.commit_group;\n");                              \
    } while (0)

    LOAD_TILE(0, 0);

    for (int kt = 0; kt < NKT; kt++) {
        const int cur = kt & 1;
        if (kt + 1 < NKT) {
            LOAD_TILE(kt + 1, cur ^ 1);
            asm volatile("cp.async.wait_group 1;\n");
        } else {
            asm volatile("cp.async.wait_group 0;\n");
        }
        __syncthreads();

#pragma unroll
        for (int s = 0; s < 4; s++) {       // 4 k16 steps per BK=64
            unsigned a[2][4], bf[4][2];
#pragma unroll
            for (int mt = 0; mt < 2; mt++) {
                const int mr  = m0w + mt * 16 + r;
                const int idx = ((s ^ (mr & 3)) << 2) | q;
                const uint2 va0 = SA[cur][mr][idx];
                const uint2 va1 = SA[cur][mr + 8][idx];
                a[mt][0] = va0.x; a[mt][1] = va1.x; a[mt][2] = va0.y; a[mt][3] = va1.y;
            }
#pragma unroll
            for (int nt = 0; nt < 4; nt++) {
                const int nc  = n0w + nt * 8 + r;
                const uint2 vb = SB[cur][nc][((s ^ (nc & 3)) << 2) | q];
                bf[nt][0] = vb.x; bf[nt][1] = vb.y;
            }
#pragma unroll
            for (int mt = 0; mt < 2; mt++)
#pragma unroll
                for (int nt = 0; nt < 4; nt++)
                    mma_f16(acc[mt][nt], a[mt], bf[nt]);
        }
        __syncthreads();
    }

    // epilogue: add bias (fp32), write fp32
#pragma unroll
    for (int mt = 0; mt < 2; mt++) {
        const int gm0 = m0 + m0w + mt * 16 + r;
#pragma unroll
        for (int nt = 0; nt < 4; nt++) {
            const int gf = f0 + n0w + nt * 8 + 2 * q;
            const float2 bvv = *reinterpret_cast<const float2*>(bias + gf);
            float2 o0, o1;
            o0.x = acc[mt][nt][0] + bvv.x;
            o0.y = acc[mt][nt][1] + bvv.y;
            o1.x = acc[mt][nt][2] + bvv.x;
            o1.y = acc[mt][nt][3] + bvv.y;
            *reinterpret_cast<float2*>(C + (size_t)gm0 * FF + gf) = o0;
            *reinterpret_cast<float2*>(C + (size_t)(gm0 + 8) * FF + gf) = o1;
        }
    }
#undef LOAD_TILE
}

// ---------------------------------------------------------------------------
// Block reduction helper: 128 threads (4 warps)
// ---------------------------------------------------------------------------
__device__ __forceinline__ float block_sum128(float v, float* red, int tid) {
#pragma unroll
    for (int o = 16; o > 0; o >>= 1) v += __shfl_xor_sync(0xffffffffu, v, o);
    if ((tid & 31) == 0) red[tid >> 5] = v;
    __syncthreads();
    v = red[0] + red[1] + red[2] + red[3];
    __syncthreads();
    return v;
}

__device__ __forceinline__ float gelu_exact(float y) {
    return 0.5f * y * (1.0f + erff(y * 0.70710678118654752f));
}

// LayerNorm + exact GELU; reads fp32, writes fp16 pair-permuted (for conv2).
__global__ void __launch_bounds__(128) ln_gelu_kernel(
    const float* __restrict__ h, const float* __restrict__ g, const float* __restrict__ bb,
    __half* __restrict__ oh) {
    __shared__ float red[4];
    const int row = blockIdx.x, tid = threadIdx.x;
    const float* p = h + (size_t)row * FF;
    __half* po = oh + (size_t)row * FF;
    float v0 = p[tid], v1 = p[tid + 128], v2 = p[tid + 256];
    const float mu = block_sum128(v0 + v1 + v2, red, tid) * (1.0f / FF);
    const float d0 = v0 - mu, d1 = v1 - mu, d2 = v2 - mu;
    const float var = block_sum128(d0 * d0 + d1 * d1 + d2 * d2, red, tid) * (1.0f / FF);
    const float rs = rsqrtf(var + 1e-5f);
    const float y0 = d0 * rs * g[tid] + bb[tid];
    const float y1 = d1 * rs * g[tid + 128] + bb[tid + 128];
    const float y2 = d2 * rs * g[tid + 256] + bb[tid + 256];
    po[permH(tid)]       = __float2half_rn(gelu_exact(y0));
    po[permH(tid + 128)] = __float2half_rn(gelu_exact(y1));
    po[permH(tid + 256)] = __float2half_rn(gelu_exact(y2));
}

// LayerNorm + GELU + linear(384->1) + ReLU -> length[row]
__global__ void __launch_bounds__(128) ln_gelu_lin_kernel(
    const float* __restrict__ h, const float* __restrict__ g, const float* __restrict__ bb,
    const float* __restrict__ lw, const float* __restrict__ lb, float* __restrict__ lenout) {
    __shared__ float red[4];
    const int row = blockIdx.x, tid = threadIdx.x;
    const float* p = h + (size_t)row * FF;
    float v0 = p[tid], v1 = p[tid + 128], v2 = p[tid + 256];
    const float mu = block_sum128(v0 + v1 + v2, red, tid) * (1.0f / FF);
    const float d0 = v0 - mu, d1 = v1 - mu, d2 = v2 - mu;
    const float var = block_sum128(d0 * d0 + d1 * d1 + d2 * d2, red, tid) * (1.0f / FF);
    const float rs = rsqrtf(var + 1e-5f);
    const float q0 = gelu_exact(d0 * rs * g[tid] + bb[tid]);
    const float q1 = gelu_exact(d1 * rs * g[tid + 128] + bb[tid + 128]);
    const float q2 = gelu_exact(d2 * rs * g[tid + 256] + bb[tid + 256]);
    const float dot = block_sum128(q0 * lw[tid] + q1 * lw[tid + 128] + q2 * lw[tid + 256],
                                   red, tid);
    if (tid == 0) lenout[row] = fmaxf(dot + lb[0], 0.0f);
}

// ---------------------------------------------------------------------------
// Duration scan + token map. One block per batch, 512 threads.
// ---------------------------------------------------------------------------
__global__ void __launch_bounds__(512) build_tok_kernel(
    const float* __restrict__ td, int* __restrict__ tok) {
    __shared__ int sc[TT];
    const int b = blockIdx.x, t = threadIdx.x;
    const int d = (int)rintf(expf(td[b * TT + t]));
    sc[t] = d;
    __syncthreads();
    for (int off = 1; off < TT; off <<= 1) {
        int v = sc[t];
        int add = (t >= off) ? sc[t - off] : 0;
        __syncthreads();
        sc[t] = v + add;
        __syncthreads();
    }
    const int end = sc[t];
    const int start = end - d;
    for (int l = start; l < end; l++) tok[b * LL + l] = t;
    __syncthreads();
    const int total = sc[TT - 1];
    for (int l = total + t; l < LL; l += TT) tok[b * LL + l] = -1;
}

// ---------------------------------------------------------------------------
// Expansion: out[b,l,:] = x[b,tok[b][l],:] (or zeros). float4 per thread.
// ---------------------------------------------------------------------------
__global__ void __launch_bounds__(256) expand_kernel(
    const float* __restrict__ x, const int* __restrict__ tok, float* __restrict__ out) {
    const unsigned idx = blockIdx.x * 256u + threadIdx.x;
    const int h4 = idx % H4;
    const int l  = (idx / H4) & (LL - 1);
    const int b  = idx / (H4 * LL);
    const int t  = tok[b * LL + l];
    float4 v = make_float4(0.f, 0.f, 0.f, 0.f);
    if (t >= 0)
        v = reinterpret_cast<const float4*>(x)[(size_t)(b * TT + t) * H4 + h4];
    reinterpret_cast<float4*>(out)[idx] = v;
}

// ---------------------------------------------------------------------------
extern "C" void kernel_launch(void* const* d_in, const int* in_sizes, int n_in,
                              void* d_out, int out_size) {
    const float* x   = (const float*)d_in[0];
    const float* td  = (const float*)d_in[1];
    const float* w1  = (const float*)d_in[2];
    const float* b1  = (const float*)d_in[3];
    const float* g1  = (const float*)d_in[4];
    const float* bb1 = (const float*)d_in[5];
    const float* w2  = (const float*)d_in[6];
    const float* b2  = (const float*)d_in[7];
    const float* g2  = (const float*)d_in[8];
    const float* bb2 = (const float*)d_in[9];
    const float* lw  = (const float*)d_in[10];
    const float* lb  = (const float*)d_in[11];

    float* out = (float*)d_out;
    float* lenout = out + OUT_OFF;

    __half *wt1p, *wt2p, *xhp, *h1hp;
    float *h1p, *h2p;
    int* tokp;
    cudaGetSymbolAddress((void**)&wt1p, g_wt1h);
    cudaGetSymbolAddress((void**)&wt2p, g_wt2h);
    cudaGetSymbolAddress((void**)&xhp,  g_xh);
    cudaGetSymbolAddress((void**)&h1p,  g_h1);
    cudaGetSymbolAddress((void**)&h1hp, g_h1h);
    cudaGetSymbolAddress((void**)&h2p,  g_h2);
    cudaGetSymbolAddress((void**)&tokp, g_tok);

    round_x_kernel<<<(BT * HH) / 256, 256>>>(x, xhp);
    wtrans_kernel<<<(2 * FF * HH * KK3) / 256, 256>>>(w1, w2, wt1p, wt2p);

    dim3 ggrid(FF / BN, BT / BM);   // (6, 64)
    conv_gemm_kernel<<<ggrid, 256>>>(xhp, wt1p, b1, h1p);
    ln_gelu_kernel<<<BT, 128>>>(h1p, g1, bb1, h1hp);
    conv_gemm_kernel<<<ggrid, 256>>>(h1hp, wt2p, b2, h2p);
    ln_gelu_lin_kernel<<<BT, 128>>>(h2p, g2, bb2, lw, lb, lenout);

    build_tok_kernel<<<BB, TT>>>(td, tokp);
    expand_kernel<<<(BB * LL * H4) / 256, 256>>>(x, tokp, out);
}